// round 13
// baseline (speedup 1.0000x reference)
#include <cuda_runtime.h>
#include <cuda_bf16.h>

#define BB 16
#define NN 4096
#define DD 256
#define BN (BB * NN)
#define EPSF 1e-6f
#define KSPL 4
#define NKV (NN / KSPL)

typedef unsigned short u16;
typedef unsigned int u32;

// ---------------- scratch (device globals; allocation-free) ----------------
__device__ u16 g_q_h[(size_t)BN * DD];                // Q [n,k] hi
__device__ u16 g_k_h[(size_t)BN * DD];                // K [n,k] hi
__device__ u16 g_wqt_h[DD * DD];                      // WqT [e,k] hi
__device__ u16 g_wkt_h[DD * DD];                      // WkT [e,k] hi
__device__ u16 g_phiq_h[(size_t)BN * DD];             // [n,e] hi
__device__ u16 g_phikt_h[(size_t)BN * DD];            // phi_k^T [b,e,n] hi
__device__ u16 g_e_h[(size_t)BN * DD];                // E^T [b,e,n] hi
__device__ float g_vt[(size_t)BN * DD];               // V^T [b,e,n]
__device__ float g_sm[BB * DD];                       // softmax denoms
__device__ float g_rs[BB * NN];                       // phi_q row sums
__device__ float g_kvp[(size_t)KSPL * BB * DD * DD];  // partial KV^T
__device__ u16 g_kvt_h[(size_t)BB * DD * DD];         // KV^T [b,e,d] hi

// ---------------- helpers ----------------
__device__ __forceinline__ float sigmoidf_(float x) { return 1.f / (1.f + __expf(-x)); }

__device__ __forceinline__ u32 smem_u32(const void* p) {
    u32 a;
    asm("{ .reg .u64 t; cvta.to.shared.u64 t, %1; cvt.u32.u64 %0, t; }" : "=r"(a) : "l"(p));
    return a;
}

// store fp32 pair as bf16 hi
__device__ __forceinline__ void store_h(u16* ph, size_t idx, float v0, float v1) {
    __nv_bfloat162 h = __floats2bfloat162_rn(v0, v1);
    *(u32*)(ph + idx) = *(u32*)&h;
}

#define MMA16816(cc, aa, b0, b1)                                               \
    asm volatile("mma.sync.aligned.m16n8k16.row.col.f32.bf16.bf16.f32 "        \
                 "{%0,%1,%2,%3}, {%4,%5,%6,%7}, {%8,%9}, {%0,%1,%2,%3};"       \
                 : "+f"((cc)[0]), "+f"((cc)[1]), "+f"((cc)[2]), "+f"((cc)[3])  \
                 : "r"((aa)[0]), "r"((aa)[1]), "r"((aa)[2]), "r"((aa)[3]),     \
                   "r"(b0), "r"(b1))

#define LDSM4(rr, addr)                                                        \
    asm volatile("ldmatrix.sync.aligned.m8n8.x4.shared.b16 {%0,%1,%2,%3}, [%4];" \
                 : "=r"((rr)[0]), "=r"((rr)[1]), "=r"((rr)[2]), "=r"((rr)[3])  \
                 : "r"(addr))

#define MMAALL(AF, BF)                                                         \
    _Pragma("unroll") for (int mi = 0; mi < 4; mi++)                           \
    _Pragma("unroll") for (int nj = 0; nj < 4; nj++)                           \
        MMA16816(c[mi][nj], AF[mi], BF[nj >> 1][nj & 1], BF[nj >> 1][(nj & 1) + 2]);

// ---------------------------------------------------------------------------
// Register-prefetch GEMM core: 128x128 block tile, 8 warps (2m x 4n),
// warp tile 64x32, K chunk 32, single-plane bf16, fp32 accum.
// Next chunk's LDGs are issued into registers before computing the current
// chunk from smem -> global-load latency overlaps LDSM+MMA. No cp.async.
// Smem: 2 tiles of 128 rows x 40 u16 (32 data + 8 pad) = 20 KB static.
// ---------------------------------------------------------------------------
#define GEMM_PREF(KTOT, gA, lda, gB, ldb)                                      \
    __shared__ u16 sA[128 * 40], sB[128 * 40];                                 \
    float c[4][4][4];                                                          \
    _Pragma("unroll") for (int i_ = 0; i_ < 4; i_++)                           \
    _Pragma("unroll") for (int j_ = 0; j_ < 4; j_++)                           \
    _Pragma("unroll") for (int r_ = 0; r_ < 4; r_++) c[i_][j_][r_] = 0.f;      \
    const int lane = tid & 31, widx = tid >> 5;                                \
    const int wm = widx >> 2, wn = widx & 3;                                   \
    const u32 frow = (u32)(lane & 15) * 80 + (u32)(lane >> 4) * 16;            \
    const u32 uA = smem_u32(sA) + wm * 64 * 80 + frow;                         \
    const u32 uB = smem_u32(sB) + wn * 32 * 80 + frow;                         \
    const int prow = tid >> 1, poff = (tid & 1) * 16;                          \
    const u16* gpa = (gA) + (size_t)prow * (lda) + poff;                       \
    const u16* gpb = (gB) + (size_t)prow * (ldb) + poff;                       \
    u16* dpa = sA + prow * 40 + poff;                                          \
    u16* dpb = sB + prow * 40 + poff;                                          \
    uint4 ra0 = *(const uint4*)(gpa);                                          \
    uint4 ra1 = *(const uint4*)(gpa + 8);                                      \
    uint4 rb0 = *(const uint4*)(gpb);                                          \
    uint4 rb1 = *(const uint4*)(gpb + 8);                                      \
    const int nch = (KTOT) >> 5;                                               \
    for (int ci = 0; ci < nch; ci++) {                                         \
        __syncthreads();                                                       \
        *(uint4*)(dpa) = ra0; *(uint4*)(dpa + 8) = ra1;                        \
        *(uint4*)(dpb) = rb0; *(uint4*)(dpb + 8) = rb1;                        \
        __syncthreads();                                                       \
        if (ci + 1 < nch) {                                                    \
            int kk = (ci + 1) << 5;                                            \
            ra0 = *(const uint4*)(gpa + kk);                                   \
            ra1 = *(const uint4*)(gpa + kk + 8);                               \
            rb0 = *(const uint4*)(gpb + kk);                                   \
            rb1 = *(const uint4*)(gpb + kk + 8);                               \
        }                                                                      \
        _Pragma("unroll")                                                      \
        for (int s = 0; s < 2; s++) {                                          \
            u32 ah[4][4], bb[2][4];                                            \
            LDSM4(bb[0], uB + s * 32);                                         \
            LDSM4(bb[1], uB + 16 * 80 + s * 32);                               \
            _Pragma("unroll") for (int mi = 0; mi < 4; mi++)                   \
                LDSM4(ah[mi], uA + mi * 16 * 80 + s * 32);                     \
            MMAALL(ah, bb)                                                     \
        }                                                                      \
    }

// epilogue loop; variadic so bodies may contain top-level commas
#define EPILOOP(...)                                                           \
    _Pragma("unroll") for (int mi = 0; mi < 4; mi++)                           \
    _Pragma("unroll") for (int nj = 0; nj < 4; nj++) {                         \
        int r0 = wm * 64 + mi * 16 + (lane >> 2);                              \
        int cc0 = wn * 32 + nj * 8 + ((lane & 3) << 1);                        \
        __VA_ARGS__                                                            \
    }

// ---------------------------------------------------------------------------
// prepasses
// ---------------------------------------------------------------------------
__global__ void __launch_bounds__(256)
k_cvt_hi(const float* __restrict__ X, u16* __restrict__ xh)
{
    size_t i = ((size_t)blockIdx.x * 256 + threadIdx.x) * 8;
    float4 a = *(const float4*)(X + i);
    float4 b = *(const float4*)(X + i + 4);
    __nv_bfloat162 h0 = __floats2bfloat162_rn(a.x, a.y);
    __nv_bfloat162 h1 = __floats2bfloat162_rn(a.z, a.w);
    __nv_bfloat162 h2 = __floats2bfloat162_rn(b.x, b.y);
    __nv_bfloat162 h3 = __floats2bfloat162_rn(b.z, b.w);
    *(uint4*)(xh + i) = make_uint4(*(u32*)&h0, *(u32*)&h1, *(u32*)&h2, *(u32*)&h3);
}

// WT hi [e,k] from W [k,e]
__global__ void k_wprep(const float* __restrict__ Wq, const float* __restrict__ Wk)
{
    int e = blockIdx.x, k = threadIdx.x;
    __nv_bfloat16 qh = __float2bfloat16(Wq[(size_t)k * DD + e]);
    __nv_bfloat16 kh = __float2bfloat16(Wk[(size_t)k * DD + e]);
    g_wqt_h[e * DD + k] = *(u16*)&qh;
    g_wkt_h[e * DD + k] = *(u16*)&kh;
}

// V transpose: V[b,n,e] -> V^T[b,e,n]
__global__ void k_transV(const float* __restrict__ V)
{
    __shared__ float t[32][33];
    int n0 = blockIdx.x * 32, e0 = blockIdx.y * 32, b = blockIdx.z;
    int tx = threadIdx.x, ty = threadIdx.y;
#pragma unroll
    for (int i = 0; i < 4; i++)
        t[ty + 8 * i][tx] = V[((size_t)b * NN + n0 + ty + 8 * i) * DD + e0 + tx];
    __syncthreads();
#pragma unroll
    for (int i = 0; i < 4; i++)
        g_vt[((size_t)b * DD + e0 + ty + 8 * i) * NN + n0 + tx] = t[tx][ty + 8 * i];
}

// ---------------------------------------------------------------------------
// phi_q[n,e] = sigmoid(Q@Wq + bq).  A=Q[n,k] hi, B=WqT[e,k] hi
// ---------------------------------------------------------------------------
__global__ void __launch_bounds__(256, 2)
k_phiq(const float* __restrict__ bq)
{
    const int tid = threadIdx.x;
    const int m0 = blockIdx.x * 128;   // global n
    const int e0 = blockIdx.y * 128;

    GEMM_PREF(DD, g_q_h + (size_t)m0 * DD, DD, g_wqt_h + (size_t)e0 * DD, DD)

    EPILOOP(
        int e = e0 + cc0;
        float2 bqe = *(const float2*)(bq + e);
        int n0g = m0 + r0;
        store_h(g_phiq_h, (size_t)n0g * DD + e,
                sigmoidf_(c[mi][nj][0] + bqe.x), sigmoidf_(c[mi][nj][1] + bqe.y));
        store_h(g_phiq_h, (size_t)(n0g + 8) * DD + e,
                sigmoidf_(c[mi][nj][2] + bqe.x), sigmoidf_(c[mi][nj][3] + bqe.y));
    )
}

// ---------------------------------------------------------------------------
// phi_k^T[b,e,n] = sigmoid(K@Wk + bk)^T.  A=WkT[e,k] hi, B=K[n,k] hi
// ---------------------------------------------------------------------------
__global__ void __launch_bounds__(256, 2)
k_phik(const float* __restrict__ bk)
{
    const int tid = threadIdx.x;
    const int n0 = blockIdx.x * 128;   // global n
    const int m0e = blockIdx.y * 128;  // e

    GEMM_PREF(DD, g_wkt_h + (size_t)m0e * DD, DD, g_k_h + (size_t)n0 * DD, DD)

    EPILOOP(
        int er = m0e + r0;
        int gn = n0 + cc0;
        int b = gn >> 12;
        int nl = gn & (NN - 1);
        float b0 = bk[er];
        float b1 = bk[er + 8];
        store_h(g_phikt_h, ((size_t)b * DD + er) * NN + nl,
                sigmoidf_(c[mi][nj][0] + b0), sigmoidf_(c[mi][nj][1] + b0));
        store_h(g_phikt_h, ((size_t)b * DD + er + 8) * NN + nl,
                sigmoidf_(c[mi][nj][2] + b1), sigmoidf_(c[mi][nj][3] + b1));
    )
}

// ---------------------------------------------------------------------------
// per (b,e): colsum(phi_k) -> inv; E = exp(phi_k*V*inv); rowsum(E) -> sm
// ---------------------------------------------------------------------------
__global__ void __launch_bounds__(256) k_cs_exp()
{
    __shared__ float red[256];
    const int e = blockIdx.x, b = blockIdx.y, tid = threadIdx.x;
    const size_t base = ((size_t)b * DD + e) * NN;
    const u16* ph = g_phikt_h + base;
    const float* vt = g_vt + base;

    float pkx[8], pky[8];
    float s = 0.f;
#pragma unroll
    for (int i = 0; i < 8; i++) {
        int n = i * 512 + tid * 2;
        u32 hp = *(const u32*)(ph + n);
        float2 hf = __bfloat1622float2(*(__nv_bfloat162*)&hp);
        pkx[i] = hf.x;
        pky[i] = hf.y;
        s += pkx[i] + pky[i];
    }
    red[tid] = s; __syncthreads();
    for (int o = 128; o > 0; o >>= 1) { if (tid < o) red[tid] += red[tid + o]; __syncthreads(); }
    const float inv = 1.f / (red[0] + EPSF);
    __syncthreads();

    float s2 = 0.f;
#pragma unroll
    for (int i = 0; i < 8; i++) {
        int n = i * 512 + tid * 2;
        float2 vv = *(const float2*)(vt + n);
        float E0 = __expf(pkx[i] * vv.x * inv);
        float E1 = __expf(pky[i] * vv.y * inv);
        store_h(g_e_h, base + n, E0, E1);
        s2 += E0 + E1;
    }
    red[tid] = s2; __syncthreads();
    for (int o = 128; o > 0; o >>= 1) { if (tid < o) red[tid] += red[tid + o]; __syncthreads(); }
    if (tid == 0) g_sm[b * DD + e] = red[0];
}

// row sums of phi_q over d (warp per row)
__global__ void __launch_bounds__(256) k_rowsum()
{
    const int row = blockIdx.x * 8 + (threadIdx.x >> 5);
    const int lane = threadIdx.x & 31;
    const u16* ph = g_phiq_h + (size_t)row * DD;
    float s = 0.f;
#pragma unroll
    for (int i = 0; i < 4; i++) {
        int j2 = (lane + 32 * i) * 2;
        u32 hp = *(const u32*)(ph + j2);
        float2 hf = __bfloat1622float2(*(__nv_bfloat162*)&hp);
        s += hf.x + hf.y;
    }
#pragma unroll
    for (int o = 16; o > 0; o >>= 1) s += __shfl_down_sync(0xffffffffu, s, o);
    if (lane == 0) g_rs[row] = s;
}

// ---------------------------------------------------------------------------
// KV partial: kvp[spl,b,e,d] = sum_{n in slice} E^T[e,n]*phi_k^T[d,n]
// ---------------------------------------------------------------------------
__global__ void __launch_bounds__(256, 2) k_kv()
{
    const int tid = threadIdx.x;
    const int d0 = blockIdx.x * 128;
    const int e0 = blockIdx.y * 128;
    const int b = blockIdx.z >> 2;
    const int spl = blockIdx.z & 3;
    const size_t abase = ((size_t)b * DD + e0) * NN + spl * NKV;
    const size_t bbase = ((size_t)b * DD + d0) * NN + spl * NKV;

    GEMM_PREF(NKV, g_e_h + abase, NN, g_phikt_h + bbase, NN)

    float* dst = g_kvp + (size_t)(spl * BB + b) * DD * DD;
    EPILOOP(
        int e = e0 + r0;
        int d = d0 + cc0;
        *(float2*)(dst + (size_t)e * DD + d) = make_float2(c[mi][nj][0], c[mi][nj][1]);
        *(float2*)(dst + (size_t)(e + 8) * DD + d) = make_float2(c[mi][nj][2], c[mi][nj][3]);
    )
}

// merge split-K, divide by sm[b,e], store KV^T [b,e,d] hi
__global__ void __launch_bounds__(256) k_kvmerge()
{
    const size_t idx2 = ((size_t)blockIdx.x * 256 + threadIdx.x) * 2;
    const size_t S = (size_t)BB * DD * DD;
    const int e = (int)((idx2 >> 8) & 255);
    const int b = (int)(idx2 >> 16);
    float inv = 1.f / g_sm[b * DD + e];
    float2 s0 = *(const float2*)(g_kvp + idx2);
    float2 s1 = *(const float2*)(g_kvp + S + idx2);
    float2 s2 = *(const float2*)(g_kvp + 2 * S + idx2);
    float2 s3 = *(const float2*)(g_kvp + 3 * S + idx2);
    float v0 = (s0.x + s1.x + s2.x + s3.x) * inv;
    float v1 = (s0.y + s1.y + s2.y + s3.y) * inv;
    store_h(g_kvt_h, idx2, v0, v1);
}

// ---------------------------------------------------------------------------
// out[n,e] = sigmoid(rs)/(rs+eps) * sum_d phi_q[n,d]*KV^T[e,d]
// ---------------------------------------------------------------------------
__global__ void __launch_bounds__(256, 2) k_out(float* __restrict__ out)
{
    const int tid = threadIdx.x;
    const int m0 = blockIdx.x * 128;   // global n
    const int e0 = blockIdx.y * 128;
    const int b = m0 >> 12;
    const size_t abase = (size_t)m0 * DD;
    const size_t bbase = ((size_t)b * DD + e0) * DD;

    GEMM_PREF(DD, g_phiq_h + abase, DD, g_kvt_h + bbase, DD)

    EPILOOP(
        int ng = m0 + r0;
        int e = e0 + cc0;
        float rs0 = g_rs[ng];
        float rs1 = g_rs[ng + 8];
        float s0 = sigmoidf_(rs0) / (rs0 + EPSF);
        float s1 = sigmoidf_(rs1) / (rs1 + EPSF);
        *(float2*)(out + (size_t)ng * DD + e) =
            make_float2(c[mi][nj][0] * s0, c[mi][nj][1] * s0);
        *(float2*)(out + (size_t)(ng + 8) * DD + e) =
            make_float2(c[mi][nj][2] * s1, c[mi][nj][3] * s1);
    )
}

// ---------------------------------------------------------------------------
extern "C" void kernel_launch(void* const* d_in, const int* in_sizes, int n_in,
                              void* d_out, int out_size)
{
    const float* Q  = (const float*)d_in[0];
    const float* K  = (const float*)d_in[1];
    const float* V  = (const float*)d_in[2];
    const float* Wq = (const float*)d_in[3];
    const float* bq = (const float*)d_in[4];
    const float* Wk = (const float*)d_in[5];
    const float* bk = (const float*)d_in[6];
    float* out = (float*)d_out;

    k_cvt_hi<<<(BN * DD) / 2048, 256>>>(Q, g_q_h);
    k_cvt_hi<<<(BN * DD) / 2048, 256>>>(K, g_k_h);
    k_wprep<<<DD, 256>>>(Wq, Wk);
    k_transV<<<dim3(NN / 32, DD / 32, BB), dim3(32, 8)>>>(V);

    k_phik<<<dim3(BN / 128, 2), 256>>>(bk);
    k_phiq<<<dim3(BN / 128, 2), 256>>>(bq);

    k_cs_exp<<<dim3(DD, BB), 256>>>();
    k_rowsum<<<BN / 8, 256>>>();

    k_kv<<<dim3(2, 2, BB * KSPL), 256>>>();
    k_kvmerge<<<(BB * DD * DD) / 512, 256>>>();

    k_out<<<dim3(BN / 128, 2), 256>>>(out);
}